// round 5
// baseline (speedup 1.0000x reference)
#include <cuda_runtime.h>

#define Bsz 2
#define Ssz 256
#define Dsz 768
#define NV  765            // valid spans per batch
#define TOT 32896          // S*(S+1)/2
#define PD  128
#define KSPLIT 3
#define KH  256            // 768 / KSPLIT
#define HS  393216L        // Bsz*Ssz*Dsz

typedef unsigned long long ull;

// Scratch: g_H/g_A layout [ks(3)][z(2)][row(512)][n(768)] (K-split partials)
__device__ float g_H[3 * 2 * Bsz * Ssz * Dsz];
__device__ float g_A[3 * 2 * Bsz * Ssz * Dsz];
__device__ float g_W3[3*Dsz];
__device__ float g_C[4*Dsz];          // 0..2: (W3[w]+b_span)@w_p1+b_p1 ; 3: cpad
__device__ float g_L[1028];
__device__ __align__(16) float g_projpad[PD];
__device__ float g_zero[Dsz];         // statically zero — never written

// ---------------------------------------------------------------------------
__device__ __forceinline__ ull pk2(float x) {
    ull r; asm("mov.b64 %0, {%1, %1};" : "=l"(r) : "f"(x)); return r;
}
__device__ __forceinline__ void fma2(ull& d, ull a, ull b) {
    asm("fma.rn.f32x2 %0, %1, %2, %0;" : "+l"(d) : "l"(a), "l"(b));
}

#define RAW_BYTES (16*132*8 + 16*128*4)   // AsU (ull, padded) + Bs

// ---------------------------------------------------------------------------
// SGEMM tile body: 128(M) x 128(N), KT=16, 256 thr, 8x4 f32x2 per thread.
// e in [0,144): nb = e%6, mb = (e/6)%4, zi = e/24 -> z = zi/3, ks = zi%3.
// Writes C partial to Cc + z*HS + ks*2*HS.
// ---------------------------------------------------------------------------
__device__ __forceinline__ void sgemm_body(
    int e, const float* __restrict__ A,
    const float* __restrict__ Ax1, const float* __restrict__ Ax2, long sAz,
    const float* __restrict__ Bm, long sBz, float* __restrict__ Cc, char* raw)
{
    ull   (*AsU)[132] = (ull(*)[132])raw;
    float (*Bs)[128]  = (float(*)[128])(raw + 16*132*8);

    const int nb = e % 6, mb = (e / 6) % 4, zi = e / 24;
    const int z = zi / KSPLIT, ks = zi % KSPLIT;
    const int kbase = ks * KH;

    A += (long)z * sAz;
    if (Ax1) { Ax1 += (long)z * sAz; Ax2 += (long)z * sAz; }
    Bm += (long)z * sBz;
    Cc += (long)z * HS + (long)ks * 2 * HS;

    const int tid = threadIdx.x;
    const int tx = tid & 15, ty = tid >> 4;
    const int row0 = mb * 128, col0 = nb * 128;
    const int m_a = tid >> 1, kh = (tid & 1) * 8;   // A loader: row, k-half
    const int kk0 = tid >> 5, nq0 = tid & 31;       // B loader: rows kk0, kk0+8

    ull acc[8][4] = {};
    float4 pa0, pa1, pb0, pb1;

    // prefetch iter 0
    {
        long ab = (long)(row0 + m_a) * Dsz + kbase + kh;
        pa0 = *(const float4*)(A + ab);
        pa1 = *(const float4*)(A + ab + 4);
        if (Ax1) {
            float4 q0 = *(const float4*)(Ax1 + ab);
            float4 q1 = *(const float4*)(Ax1 + ab + 4);
            float4 r0 = *(const float4*)(Ax2 + ab);
            float4 r1 = *(const float4*)(Ax2 + ab + 4);
            pa0.x += q0.x + r0.x; pa0.y += q0.y + r0.y;
            pa0.z += q0.z + r0.z; pa0.w += q0.w + r0.w;
            pa1.x += q1.x + r1.x; pa1.y += q1.y + r1.y;
            pa1.z += q1.z + r1.z; pa1.w += q1.w + r1.w;
        }
        pb0 = *(const float4*)(Bm + (long)(kbase + kk0) * Dsz + col0 + nq0 * 4);
        pb1 = *(const float4*)(Bm + (long)(kbase + kk0 + 8) * Dsz + col0 + nq0 * 4);
    }

    const int ITERS = KH / 16;   // 16
    for (int it = 0; it < ITERS; it++) {
        __syncthreads();
        AsU[kh + 0][m_a] = pk2(pa0.x);
        AsU[kh + 1][m_a] = pk2(pa0.y);
        AsU[kh + 2][m_a] = pk2(pa0.z);
        AsU[kh + 3][m_a] = pk2(pa0.w);
        AsU[kh + 4][m_a] = pk2(pa1.x);
        AsU[kh + 5][m_a] = pk2(pa1.y);
        AsU[kh + 6][m_a] = pk2(pa1.z);
        AsU[kh + 7][m_a] = pk2(pa1.w);
        ((float4*)&Bs[kk0][0])[nq0]     = pb0;
        ((float4*)&Bs[kk0 + 8][0])[nq0] = pb1;
        __syncthreads();

        if (it + 1 < ITERS) {
            int kb = kbase + (it + 1) * 16;
            long ab = (long)(row0 + m_a) * Dsz + kb + kh;
            pa0 = *(const float4*)(A + ab);
            pa1 = *(const float4*)(A + ab + 4);
            if (Ax1) {
                float4 q0 = *(const float4*)(Ax1 + ab);
                float4 q1 = *(const float4*)(Ax1 + ab + 4);
                float4 r0 = *(const float4*)(Ax2 + ab);
                float4 r1 = *(const float4*)(Ax2 + ab + 4);
                pa0.x += q0.x + r0.x; pa0.y += q0.y + r0.y;
                pa0.z += q0.z + r0.z; pa0.w += q0.w + r0.w;
                pa1.x += q1.x + r1.x; pa1.y += q1.y + r1.y;
                pa1.z += q1.z + r1.z; pa1.w += q1.w + r1.w;
            }
            pb0 = *(const float4*)(Bm + (long)(kb + kk0) * Dsz + col0 + nq0 * 4);
            pb1 = *(const float4*)(Bm + (long)(kb + kk0 + 8) * Dsz + col0 + nq0 * 4);
        }

        #pragma unroll
        for (int kk = 0; kk < 16; kk++) {
            ull aa[8];
            #pragma unroll
            for (int u = 0; u < 8; u++) aa[u] = AsU[kk][ty * 8 + u];
            const ull* brow = (const ull*)&Bs[kk][0];
            #pragma unroll
            for (int v = 0; v < 4; v++) {
                ull bb = brow[tx + 16 * v];
                #pragma unroll
                for (int u = 0; u < 8; u++) fma2(acc[u][v], aa[u], bb);
            }
        }
    }

    #pragma unroll
    for (int u = 0; u < 8; u++) {
        long rbase = ((long)(row0 + ty * 8 + u) * Dsz + col0) >> 1;
        #pragma unroll
        for (int v = 0; v < 4; v++) {
            float2 r;
            asm("mov.b64 {%0, %1}, %2;" : "=f"(r.x), "=f"(r.y) : "l"(acc[u][v]));
            ((float2*)Cc)[rbase + tx + 16 * v] = r;
        }
    }
}

// ---------------------------------------------------------------------------
// GEMV-64 body: out[n0+nl] = (sum_k src(k) * W[k*ldw + n]) + bias[n]
// 256 thr = 64 n x 4 k-groups of 192.  mode 0: a1 ; 1: a1+a2 ; 2: relu(a1)
// ---------------------------------------------------------------------------
__device__ __forceinline__ void gemv_body(
    const float* __restrict__ a1, const float* __restrict__ a2, int mode,
    const float* __restrict__ W, int ldw,
    const float* __restrict__ bias, float* __restrict__ out,
    int n0, char* raw)
{
    float (*red)[64] = (float(*)[64])raw;
    const int tid = threadIdx.x;
    const int nl = tid & 63, kg = tid >> 6;
    const int n = n0 + nl;
    float s = 0.f;
    const int k0 = kg * 192;
    #pragma unroll 8
    for (int t = 0; t < 192; t++) {
        int k = k0 + t;
        float av = a1[k];
        if (mode == 1) av += a2[k];
        else if (mode == 2) av = fmaxf(av, 0.f);
        s += av * W[(long)k * ldw + n];
    }
    red[kg][nl] = s;
    __syncthreads();
    if (kg == 0)
        out[n] = red[0][nl] + red[1][nl] + red[2][nl] + red[3][nl] + bias[n];
}

// ---------------------------------------------------------------------------
// L1: [0,144) sgemm H ; [144,180) W3 ; [180,192) C-pad row
// ---------------------------------------------------------------------------
__global__ __launch_bounds__(256, 2) void L1_k(
    const float* __restrict__ hidden, const float* __restrict__ width_emb,
    const float* __restrict__ w_span, const float* __restrict__ b_span,
    const float* __restrict__ w_p1, const float* __restrict__ b_p1)
{
    __shared__ __align__(16) char raw[RAW_BYTES];
    int e = blockIdx.x;
    if (e < 144) {
        sgemm_body(e, hidden, nullptr, nullptr, 0L,
                   w_span, (long)Dsz * Dsz, g_H, raw);
    } else if (e < 180) {
        int g = e - 144, m = g / 12, nb = g % 12;
        gemv_body(width_emb + m * Dsz, nullptr, 0,
                  w_span + 2L * Dsz * Dsz, Dsz,
                  g_zero, g_W3 + m * Dsz, nb * 64, raw);
    } else {
        int nb = e - 180;
        gemv_body(b_span, nullptr, 0, w_p1, Dsz, b_p1, g_C + 3 * Dsz,
                  nb * 64, raw);
    }
}

// ---------------------------------------------------------------------------
// L2: [0,144) sgemm A ; [144,180) C rows 0..2 ; [180,182) projpad ;
//     [182,311) dots
// ---------------------------------------------------------------------------
__global__ __launch_bounds__(256, 2) void L2_k(
    const float* __restrict__ w_p1, const float* __restrict__ b_p1,
    const float* __restrict__ b_span, const float* __restrict__ w_cls,
    const float* __restrict__ b_cls, const float* __restrict__ w_p2,
    const float* __restrict__ b_p2)
{
    __shared__ __align__(16) char raw[RAW_BYTES];
    int e = blockIdx.x;
    if (e < 144) {
        sgemm_body(e, g_H, g_H + 2 * HS, g_H + 4 * HS, HS,
                   w_p1, 0L, g_A, raw);
    } else if (e < 180) {
        int g = e - 144, m = g / 12, nb = g % 12;
        gemv_body(g_W3 + m * Dsz, b_span, 1, w_p1, Dsz, b_p1,
                  g_C + m * Dsz, nb * 64, raw);
    } else if (e < 182) {
        int nb = e - 180;
        gemv_body(g_C + 3 * Dsz, nullptr, 2, w_p2, PD, b_p2, g_projpad,
                  nb * 64, raw);
    } else {
        int gw = (e - 182) * 8 + (threadIdx.x >> 5);
        int lane = threadIdx.x & 31;
        if (gw >= 1028) return;
        float s = 0.f;
        if (gw < 1024) {
            int z = gw >> 9, row = gw & 511;
            const float* base = g_H + (long)z * HS + (long)row * Dsz;
            for (int k = lane; k < Dsz; k += 32)
                s += (base[k] + base[2 * HS + k] + base[4 * HS + k]) * w_cls[k];
        } else {
            const float* v = (gw < 1027) ? (g_W3 + (gw - 1024) * Dsz) : b_span;
            for (int k = lane; k < Dsz; k += 32) s += v[k] * w_cls[k];
        }
        #pragma unroll
        for (int o = 16; o > 0; o >>= 1) s += __shfl_down_sync(0xffffffffu, s, o);
        if (lane == 0) g_L[gw] = s + (gw == 1027 ? b_cls[0] : 0.f);
    }
}

// ---------------------------------------------------------------------------
// L3: [0,96) spanproj ; [96,353) logits ; [353,8386) fillpad
// ---------------------------------------------------------------------------
__global__ __launch_bounds__(256, 2) void L3_k(
    const float* __restrict__ w_p2, const float* __restrict__ b_p2,
    float* __restrict__ out)
{
    int e = blockIdx.x;
    if (e < 96) {
        __shared__ float Xs[16][17];
        __shared__ float Ws[16][PD];
        __shared__ int offA1[16], offA2[16], offC[16];
        __shared__ long offOut[16];

        int tid = threadIdx.x;
        int m0 = e * 16;
        if (tid < 16) {
            int msp = m0 + tid;
            int b = 0, i = 0, w = 0;
            bool valid = msp < 2 * NV;
            int kv = 0;
            if (valid) {
                b = msp / NV; kv = msp - b * NV;
                if (kv < 762)      { i = kv / 3; w = kv - 3 * i; }
                else if (kv < 764) { i = 254;   w = kv - 762;   }
                else               { i = 255;   w = 0;          }
            }
            int j = i + w;
            offA1[tid] = (b * Ssz + i) * Dsz;
            offA2[tid] = (int)HS + (b * Ssz + j) * Dsz;
            offC[tid]  = w * Dsz;
            offOut[tid] = valid ? ((long)Bsz * TOT + ((long)b * TOT + kv) * PD) : -1L;
        }
        __syncthreads();

        int tx = tid & 31, ty = tid >> 5;
        float acc[2][4] = {};
        for (int k0 = 0; k0 < Dsz; k0 += 16) {
            {
                int m = tid >> 4, kk = tid & 15;
                long o1 = offA1[m] + k0 + kk, o2 = offA2[m] + k0 + kk;
                float v = g_A[o1] + g_A[o1 + 2 * HS] + g_A[o1 + 4 * HS]
                        + g_A[o2] + g_A[o2 + 2 * HS] + g_A[o2 + 4 * HS]
                        + g_C[offC[m] + k0 + kk];
                Xs[kk][m] = fmaxf(v, 0.f);
            }
            #pragma unroll
            for (int l = 0; l < 8; l++) {
                int idx = tid + l * 256;
                int kk = idx >> 7, n = idx & 127;
                Ws[kk][n] = w_p2[(long)(k0 + kk) * PD + n];
            }
            __syncthreads();
            #pragma unroll
            for (int kk = 0; kk < 16; kk++) {
                float a0 = Xs[kk][ty], a1 = Xs[kk][ty + 8];
                #pragma unroll
                for (int v = 0; v < 4; v++) {
                    float bb = Ws[kk][tx + 32 * v];
                    acc[0][v] += a0 * bb;
                    acc[1][v] += a1 * bb;
                }
            }
            __syncthreads();
        }
        #pragma unroll
        for (int u = 0; u < 2; u++) {
            int m = ty + 8 * u;
            long ob = offOut[m];
            if (ob >= 0) {
                #pragma unroll
                for (int v = 0; v < 4; v++) {
                    int n = tx + 32 * v;
                    out[ob + n] = acc[u][v] + b_p2[n];
                }
            }
        }
    } else if (e < 353) {
        int idx = (e - 96) * 256 + threadIdx.x;
        if (idx >= Bsz * TOT) return;
        int b = idx / TOT, t = idx - b * TOT;
        float v;
        if (t < NV) {
            int i, w;
            if (t < 762)      { i = t / 3; w = t - 3 * i; }
            else if (t < 764) { i = 254;  w = t - 762;   }
            else              { i = 255;  w = 0;         }
            int j = i + w;
            v = g_L[b * Ssz + i] + g_L[512 + b * Ssz + j] + g_L[1024 + w] + g_L[1027];
        } else {
            v = g_L[1027];
        }
        out[idx] = v;
    } else {
        const int PADROWS = TOT - NV;
        long idx = (long)(e - 353) * 256 + threadIdx.x;
        if (idx >= (long)Bsz * PADROWS * 32) return;
        int r = (int)(idx >> 5), c = (int)(idx & 31);
        int b = r / PADROWS;
        int kk = NV + (r - b * PADROWS);
        float4 val = ((const float4*)g_projpad)[c];
        long f4 = (long)(Bsz * TOT) / 4 + ((long)b * TOT + kk) * (PD / 4) + c;
        ((float4*)out)[f4] = val;
    }
}

// ---------------------------------------------------------------------------
extern "C" void kernel_launch(void* const* d_in, const int* in_sizes, int n_in,
                              void* d_out, int out_size)
{
    const float* hidden    = (const float*)d_in[0];
    const float* width_emb = (const float*)d_in[1];
    const float* w_span    = (const float*)d_in[2];
    const float* b_span    = (const float*)d_in[3];
    const float* w_cls     = (const float*)d_in[4];
    const float* b_cls     = (const float*)d_in[5];
    const float* w_p1      = (const float*)d_in[6];
    const float* b_p1      = (const float*)d_in[7];
    const float* w_p2      = (const float*)d_in[8];
    const float* b_p2      = (const float*)d_in[9];
    float* out = (float*)d_out;

    L1_k<<<192, 256>>>(hidden, width_emb, w_span, b_span, w_p1, b_p1);
    L2_k<<<311, 256>>>(w_p1, b_p1, b_span, w_cls, b_cls, w_p2, b_p2);
    L3_k<<<8386, 256>>>(w_p2, b_p2, out);
}

// round 6
// speedup vs baseline: 1.0250x; 1.0250x over previous
#include <cuda_runtime.h>

#define Bsz 2
#define Ssz 256
#define Dsz 768
#define NV  765            // valid spans per batch
#define TOT 32896          // S*(S+1)/2
#define PD  128
#define KSPLIT 3
#define KH  256            // 768 / KSPLIT
#define HS  393216L        // Bsz*Ssz*Dsz

typedef unsigned long long ull;

// Scratch: g_H/g_A layout [ks(3)][z(2)][row(512)][n(768)] (K-split partials)
__device__ float g_H[3 * 2 * Bsz * Ssz * Dsz];
__device__ float g_A[3 * 2 * Bsz * Ssz * Dsz];
__device__ float g_W3[3*Dsz];
__device__ float g_C[4*Dsz];          // 0..2: (W3[w]+b_span)@w_p1+b_p1 ; 3: cpad
__device__ float g_L[1028];
__device__ __align__(16) float g_projpad[PD];
__device__ float g_zero[Dsz];         // statically zero — never written

// ---------------------------------------------------------------------------
__device__ __forceinline__ ull pk2(float x) {
    ull r; asm("mov.b64 %0, {%1, %1};" : "=l"(r) : "f"(x)); return r;
}
__device__ __forceinline__ void fma2(ull& d, ull a, ull b) {
    asm("fma.rn.f32x2 %0, %1, %2, %0;" : "+l"(d) : "l"(a), "l"(b));
}
__device__ __forceinline__ float2 unpk(ull v) {
    float2 r;
    asm("mov.b64 {%0, %1}, %2;" : "=f"(r.x), "=f"(r.y) : "l"(v));
    return r;
}

// double-buffered: AsU[2][16][65] ull + Bs[2][16][128] float
#define RAW_BYTES (2*16*65*8 + 2*16*128*4)

// ---------------------------------------------------------------------------
// SGEMM tile body: 64(M) x 128(N), KT=16, 256 thr, 4x4 f32x2 per thread.
// e in [0,288): nb = e%6, mb = (e/6)%8, zi = e/48 -> z = zi/3, ks = zi%3.
// Double-buffered smem: ONE __syncthreads per K-tile.
// Thread n-mapping: cols col0 + tx*8 .. tx*8+7 (contiguous per thread).
// ---------------------------------------------------------------------------
__device__ __forceinline__ void sgemm_body(
    int e, const float* __restrict__ A,
    const float* __restrict__ Ax1, const float* __restrict__ Ax2, long sAz,
    const float* __restrict__ Bm, long sBz, float* __restrict__ Cc, char* raw)
{
    ull   (*AsU)[16][65]  = (ull(*)[16][65])raw;
    float (*Bs)[16][128]  = (float(*)[16][128])(raw + 2*16*65*8);

    const int nb = e % 6, mb = (e / 6) % 8, zi = e / 48;
    const int z = zi / KSPLIT, ks = zi % KSPLIT;
    const int kbase = ks * KH;

    A += (long)z * sAz;
    if (Ax1) { Ax1 += (long)z * sAz; Ax2 += (long)z * sAz; }
    Bm += (long)z * sBz;
    Cc += (long)z * HS + (long)ks * 2 * HS;

    const int tid = threadIdx.x;
    const int tx = tid & 15, ty = tid >> 4;
    const int row0 = mb * 64, col0 = nb * 128;
    const int m_a = tid >> 2, kq = tid & 3;      // A loader: row, float4-col
    const int kk0 = tid >> 5, nq0 = tid & 31;    // B loader: rows kk0, kk0+8

    ull acc[4][4] = {};
    float4 pa, pb0, pb1;

    // prefetch iter 0
    {
        long ab = (long)(row0 + m_a) * Dsz + kbase + kq * 4;
        pa = *(const float4*)(A + ab);
        if (Ax1) {
            float4 q1 = *(const float4*)(Ax1 + ab);
            float4 q2 = *(const float4*)(Ax2 + ab);
            pa.x += q1.x + q2.x; pa.y += q1.y + q2.y;
            pa.z += q1.z + q2.z; pa.w += q1.w + q2.w;
        }
        pb0 = *(const float4*)(Bm + (long)(kbase + kk0) * Dsz + col0 + nq0 * 4);
        pb1 = *(const float4*)(Bm + (long)(kbase + kk0 + 8) * Dsz + col0 + nq0 * 4);
    }
    // store into buffer 0
    AsU[0][kq * 4 + 0][m_a] = pk2(pa.x);
    AsU[0][kq * 4 + 1][m_a] = pk2(pa.y);
    AsU[0][kq * 4 + 2][m_a] = pk2(pa.z);
    AsU[0][kq * 4 + 3][m_a] = pk2(pa.w);
    ((float4*)&Bs[0][kk0][0])[nq0]     = pb0;
    ((float4*)&Bs[0][kk0 + 8][0])[nq0] = pb1;
    __syncthreads();

    const int ITERS = KH / 16;   // 16
    for (int it = 0; it < ITERS; it++) {
        const int cur = it & 1, nxt = cur ^ 1;

        // issue next-tile gmem loads early
        if (it + 1 < ITERS) {
            int kb = kbase + (it + 1) * 16;
            long ab = (long)(row0 + m_a) * Dsz + kb + kq * 4;
            pa = *(const float4*)(A + ab);
            if (Ax1) {
                float4 q1 = *(const float4*)(Ax1 + ab);
                float4 q2 = *(const float4*)(Ax2 + ab);
                pa.x += q1.x + q2.x; pa.y += q1.y + q2.y;
                pa.z += q1.z + q2.z; pa.w += q1.w + q2.w;
            }
            pb0 = *(const float4*)(Bm + (long)(kb + kk0) * Dsz + col0 + nq0 * 4);
            pb1 = *(const float4*)(Bm + (long)(kb + kk0 + 8) * Dsz + col0 + nq0 * 4);
        }

        // compute on current buffer
        #pragma unroll
        for (int kk = 0; kk < 16; kk++) {
            ull aa[4];
            #pragma unroll
            for (int u = 0; u < 4; u++) aa[u] = AsU[cur][kk][ty + 16 * u];
            const ulonglong2* bp = (const ulonglong2*)&Bs[cur][kk][0];
            ulonglong2 p0 = bp[tx * 2], p1 = bp[tx * 2 + 1];
            ull bb[4] = { p0.x, p0.y, p1.x, p1.y };
            #pragma unroll
            for (int v = 0; v < 4; v++)
                #pragma unroll
                for (int u = 0; u < 4; u++) fma2(acc[u][v], aa[u], bb[v]);
        }

        // store next tile into other buffer (no race: cur-compute done locally,
        // cross-warp safety via the single sync below)
        if (it + 1 < ITERS) {
            AsU[nxt][kq * 4 + 0][m_a] = pk2(pa.x);
            AsU[nxt][kq * 4 + 1][m_a] = pk2(pa.y);
            AsU[nxt][kq * 4 + 2][m_a] = pk2(pa.z);
            AsU[nxt][kq * 4 + 3][m_a] = pk2(pa.w);
            ((float4*)&Bs[nxt][kk0][0])[nq0]     = pb0;
            ((float4*)&Bs[nxt][kk0 + 8][0])[nq0] = pb1;
            __syncthreads();
        }
    }

    // store C: thread covers 8 consecutive cols at col0 + tx*8
    #pragma unroll
    for (int u = 0; u < 4; u++) {
        float* cp = Cc + (long)(row0 + ty + 16 * u) * Dsz + col0 + tx * 8;
        float2 r0 = unpk(acc[u][0]), r1 = unpk(acc[u][1]);
        float2 r2 = unpk(acc[u][2]), r3 = unpk(acc[u][3]);
        float4 s0 = { r0.x, r0.y, r1.x, r1.y };
        float4 s1 = { r2.x, r2.y, r3.x, r3.y };
        ((float4*)cp)[0] = s0;
        ((float4*)cp)[1] = s1;
    }
}

// ---------------------------------------------------------------------------
// GEMV-64 body: out[n0+nl] = (sum_k src(k) * W[k*ldw + n]) + bias[n]
// 256 thr = 64 n x 4 k-groups of 192.  mode 0: a1 ; 1: a1+a2 ; 2: relu(a1)
// ---------------------------------------------------------------------------
__device__ __forceinline__ void gemv_body(
    const float* __restrict__ a1, const float* __restrict__ a2, int mode,
    const float* __restrict__ W, int ldw,
    const float* __restrict__ bias, float* __restrict__ out,
    int n0, char* raw)
{
    float (*red)[64] = (float(*)[64])raw;
    const int tid = threadIdx.x;
    const int nl = tid & 63, kg = tid >> 6;
    const int n = n0 + nl;
    float s = 0.f;
    const int k0 = kg * 192;
    #pragma unroll 8
    for (int t = 0; t < 192; t++) {
        int k = k0 + t;
        float av = a1[k];
        if (mode == 1) av += a2[k];
        else if (mode == 2) av = fmaxf(av, 0.f);
        s += av * W[(long)k * ldw + n];
    }
    red[kg][nl] = s;
    __syncthreads();
    if (kg == 0)
        out[n] = red[0][nl] + red[1][nl] + red[2][nl] + red[3][nl] + bias[n];
}

// ---------------------------------------------------------------------------
// L1: [0,288) sgemm H ; [288,324) W3 ; [324,336) C-pad row
// ---------------------------------------------------------------------------
__global__ __launch_bounds__(256, 2) void L1_k(
    const float* __restrict__ hidden, const float* __restrict__ width_emb,
    const float* __restrict__ w_span, const float* __restrict__ b_span,
    const float* __restrict__ w_p1, const float* __restrict__ b_p1)
{
    __shared__ __align__(16) char raw[RAW_BYTES];
    int e = blockIdx.x;
    if (e < 288) {
        sgemm_body(e, hidden, nullptr, nullptr, 0L,
                   w_span, (long)Dsz * Dsz, g_H, raw);
    } else if (e < 324) {
        int g = e - 288, m = g / 12, nb = g % 12;
        gemv_body(width_emb + m * Dsz, nullptr, 0,
                  w_span + 2L * Dsz * Dsz, Dsz,
                  g_zero, g_W3 + m * Dsz, nb * 64, raw);
    } else {
        int nb = e - 324;
        gemv_body(b_span, nullptr, 0, w_p1, Dsz, b_p1, g_C + 3 * Dsz,
                  nb * 64, raw);
    }
}

// ---------------------------------------------------------------------------
// L2: [0,288) sgemm A ; [288,324) C rows 0..2 ; [324,326) projpad ;
//     [326,455) dots
// ---------------------------------------------------------------------------
__global__ __launch_bounds__(256, 2) void L2_k(
    const float* __restrict__ w_p1, const float* __restrict__ b_p1,
    const float* __restrict__ b_span, const float* __restrict__ w_cls,
    const float* __restrict__ b_cls, const float* __restrict__ w_p2,
    const float* __restrict__ b_p2)
{
    __shared__ __align__(16) char raw[RAW_BYTES];
    int e = blockIdx.x;
    if (e < 288) {
        sgemm_body(e, g_H, g_H + 2 * HS, g_H + 4 * HS, HS,
                   w_p1, 0L, g_A, raw);
    } else if (e < 324) {
        int g = e - 288, m = g / 12, nb = g % 12;
        gemv_body(g_W3 + m * Dsz, b_span, 1, w_p1, Dsz, b_p1,
                  g_C + m * Dsz, nb * 64, raw);
    } else if (e < 326) {
        int nb = e - 324;
        gemv_body(g_C + 3 * Dsz, nullptr, 2, w_p2, PD, b_p2, g_projpad,
                  nb * 64, raw);
    } else {
        int gw = (e - 326) * 8 + (threadIdx.x >> 5);
        int lane = threadIdx.x & 31;
        if (gw >= 1028) return;
        float s = 0.f;
        if (gw < 1024) {
            int z = gw >> 9, row = gw & 511;
            const float* base = g_H + (long)z * HS + (long)row * Dsz;
            for (int k = lane; k < Dsz; k += 32)
                s += (base[k] + base[2 * HS + k] + base[4 * HS + k]) * w_cls[k];
        } else {
            const float* v = (gw < 1027) ? (g_W3 + (gw - 1024) * Dsz) : b_span;
            for (int k = lane; k < Dsz; k += 32) s += v[k] * w_cls[k];
        }
        #pragma unroll
        for (int o = 16; o > 0; o >>= 1) s += __shfl_down_sync(0xffffffffu, s, o);
        if (lane == 0) g_L[gw] = s + (gw == 1027 ? b_cls[0] : 0.f);
    }
}

// ---------------------------------------------------------------------------
// L3: [0,96) spanproj ; [96,353) logits ; [353,8386) fillpad
// ---------------------------------------------------------------------------
__global__ __launch_bounds__(256, 2) void L3_k(
    const float* __restrict__ w_p2, const float* __restrict__ b_p2,
    float* __restrict__ out)
{
    int e = blockIdx.x;
    if (e < 96) {
        __shared__ float Xs[16][17];
        __shared__ float Ws[16][PD];
        __shared__ int offA1[16], offA2[16], offC[16];
        __shared__ long offOut[16];

        int tid = threadIdx.x;
        int m0 = e * 16;
        if (tid < 16) {
            int msp = m0 + tid;
            int b = 0, i = 0, w = 0;
            bool valid = msp < 2 * NV;
            int kv = 0;
            if (valid) {
                b = msp / NV; kv = msp - b * NV;
                if (kv < 762)      { i = kv / 3; w = kv - 3 * i; }
                else if (kv < 764) { i = 254;   w = kv - 762;   }
                else               { i = 255;   w = 0;          }
            }
            int j = i + w;
            offA1[tid] = (b * Ssz + i) * Dsz;
            offA2[tid] = (int)HS + (b * Ssz + j) * Dsz;
            offC[tid]  = w * Dsz;
            offOut[tid] = valid ? ((long)Bsz * TOT + ((long)b * TOT + kv) * PD) : -1L;
        }
        __syncthreads();

        int tx = tid & 31, ty = tid >> 5;
        float acc[2][4] = {};
        for (int k0 = 0; k0 < Dsz; k0 += 16) {
            {
                int m = tid >> 4, kk = tid & 15;
                long o1 = offA1[m] + k0 + kk, o2 = offA2[m] + k0 + kk;
                float v = g_A[o1] + g_A[o1 + 2 * HS] + g_A[o1 + 4 * HS]
                        + g_A[o2] + g_A[o2 + 2 * HS] + g_A[o2 + 4 * HS]
                        + g_C[offC[m] + k0 + kk];
                Xs[kk][m] = fmaxf(v, 0.f);
            }
            #pragma unroll
            for (int l = 0; l < 8; l++) {
                int idx = tid + l * 256;
                int kk = idx >> 7, n = idx & 127;
                Ws[kk][n] = w_p2[(long)(k0 + kk) * PD + n];
            }
            __syncthreads();
            #pragma unroll
            for (int kk = 0; kk < 16; kk++) {
                float a0 = Xs[kk][ty], a1 = Xs[kk][ty + 8];
                #pragma unroll
                for (int v = 0; v < 4; v++) {
                    float bb = Ws[kk][tx + 32 * v];
                    acc[0][v] += a0 * bb;
                    acc[1][v] += a1 * bb;
                }
            }
            __syncthreads();
        }
        #pragma unroll
        for (int u = 0; u < 2; u++) {
            int m = ty + 8 * u;
            long ob = offOut[m];
            if (ob >= 0) {
                #pragma unroll
                for (int v = 0; v < 4; v++) {
                    int n = tx + 32 * v;
                    out[ob + n] = acc[u][v] + b_p2[n];
                }
            }
        }
    } else if (e < 353) {
        int idx = (e - 96) * 256 + threadIdx.x;
        if (idx >= Bsz * TOT) return;
        int b = idx / TOT, t = idx - b * TOT;
        float v;
        if (t < NV) {
            int i, w;
            if (t < 762)      { i = t / 3; w = t - 3 * i; }
            else if (t < 764) { i = 254;  w = t - 762;   }
            else              { i = 255;  w = 0;         }
            int j = i + w;
            v = g_L[b * Ssz + i] + g_L[512 + b * Ssz + j] + g_L[1024 + w] + g_L[1027];
        } else {
            v = g_L[1027];
        }
        out[idx] = v;
    } else {
        const int PADROWS = TOT - NV;
        long idx = (long)(e - 353) * 256 + threadIdx.x;
        if (idx >= (long)Bsz * PADROWS * 32) return;
        int r = (int)(idx >> 5), c = (int)(idx & 31);
        int b = r / PADROWS;
        int kk = NV + (r - b * PADROWS);
        float4 val = ((const float4*)g_projpad)[c];
        long f4 = (long)(Bsz * TOT) / 4 + ((long)b * TOT + kk) * (PD / 4) + c;
        ((float4*)out)[f4] = val;
    }
}

// ---------------------------------------------------------------------------
extern "C" void kernel_launch(void* const* d_in, const int* in_sizes, int n_in,
                              void* d_out, int out_size)
{
    const float* hidden    = (const float*)d_in[0];
    const float* width_emb = (const float*)d_in[1];
    const float* w_span    = (const float*)d_in[2];
    const float* b_span    = (const float*)d_in[3];
    const float* w_cls     = (const float*)d_in[4];
    const float* b_cls     = (const float*)d_in[5];
    const float* w_p1      = (const float*)d_in[6];
    const float* b_p1      = (const float*)d_in[7];
    const float* w_p2      = (const float*)d_in[8];
    const float* b_p2      = (const float*)d_in[9];
    float* out = (float*)d_out;

    L1_k<<<336, 256>>>(hidden, width_emb, w_span, b_span, w_p1, b_p1);
    L2_k<<<455, 256>>>(w_p1, b_p1, b_span, w_cls, b_cls, w_p2, b_p2);
    L3_k<<<8386, 256>>>(w_p2, b_p2, out);
}

// round 7
// speedup vs baseline: 1.0321x; 1.0069x over previous
#include <cuda_runtime.h>

#define Bsz 2
#define Ssz 256
#define Dsz 768
#define NV  765            // valid spans per batch
#define TOT 32896          // S*(S+1)/2
#define PD  128
#define KSPLIT 3
#define KH  256            // 768 / KSPLIT
#define HS  393216L        // Bsz*Ssz*Dsz

typedef unsigned long long ull;

// Scratch: g_H/g_A layout [ks(3)][z(2)][row(512)][n(768)] (K-split partials)
__device__ float g_H[3 * 2 * Bsz * Ssz * Dsz];
__device__ float g_A[3 * 2 * Bsz * Ssz * Dsz];
__device__ float g_W3[3*Dsz];
__device__ float g_C[4*Dsz];          // 0..2: (W3[w]+b_span)@w_p1+b_p1 ; 3: cpad
__device__ float g_L[1028];
__device__ __align__(16) float g_projpad[PD];
__device__ float g_zero[Dsz];         // statically zero — never written

// ---------------------------------------------------------------------------
__device__ __forceinline__ ull pk2(float x) {
    ull r; asm("mov.b64 %0, {%1, %1};" : "=l"(r) : "f"(x)); return r;
}
__device__ __forceinline__ void fma2(ull& d, ull a, ull b) {
    asm("fma.rn.f32x2 %0, %1, %2, %0;" : "+l"(d) : "l"(a), "l"(b));
}

#define RAW_BYTES (16*65*8 + 16*128*4)   // AsU (ull, padded) + Bs

// ---------------------------------------------------------------------------
// SGEMM tile core (R4-proven shape): 64(M) x 128(N), KT=16, 256 thr,
// 4x4 f32x2 per thread.  e in [0,288): nb=e%6, mb=(e/6)%8, zi=e/48.
// Variant 1: plain A.   Variant 3: A summed from 3 K-split partials.
// ---------------------------------------------------------------------------
__device__ __forceinline__ void sgemm_compute(
    const float* __restrict__ A, const float* __restrict__ Bm,
    float* __restrict__ Cc, int kbase, int row0, int col0,
    const float* __restrict__ As1, const float* __restrict__ As2,  // may be null
    char* raw)
{
    ull   (*AsU)[65]  = (ull(*)[65])raw;
    float (*Bs)[128]  = (float(*)[128])(raw + 16*65*8);

    const int tid = threadIdx.x;
    const int tx = tid & 15, ty = tid >> 4;
    const int m_a = tid >> 2, kq = tid & 3;      // A loader
    const int kk0 = tid >> 5, nq0 = tid & 31;    // B loader

    ull acc[4][4] = {};
    float4 pa, pb0, pb1;

    {
        long ab = (long)(row0 + m_a) * Dsz + kbase + kq * 4;
        pa = *(const float4*)(A + ab);
        if (As1) {
            float4 q1 = *(const float4*)(As1 + ab);
            float4 q2 = *(const float4*)(As2 + ab);
            pa.x += q1.x + q2.x; pa.y += q1.y + q2.y;
            pa.z += q1.z + q2.z; pa.w += q1.w + q2.w;
        }
        pb0 = *(const float4*)(Bm + (long)(kbase + kk0) * Dsz + col0 + nq0 * 4);
        pb1 = *(const float4*)(Bm + (long)(kbase + kk0 + 8) * Dsz + col0 + nq0 * 4);
    }

    const int ITERS = KH / 16;   // 16
    for (int it = 0; it < ITERS; it++) {
        __syncthreads();
        AsU[kq * 4 + 0][m_a] = pk2(pa.x);
        AsU[kq * 4 + 1][m_a] = pk2(pa.y);
        AsU[kq * 4 + 2][m_a] = pk2(pa.z);
        AsU[kq * 4 + 3][m_a] = pk2(pa.w);
        ((float4*)&Bs[kk0][0])[nq0]     = pb0;
        ((float4*)&Bs[kk0 + 8][0])[nq0] = pb1;
        __syncthreads();

        if (it + 1 < ITERS) {
            int kb = kbase + (it + 1) * 16;
            long ab = (long)(row0 + m_a) * Dsz + kb + kq * 4;
            pa = *(const float4*)(A + ab);
            if (As1) {
                float4 q1 = *(const float4*)(As1 + ab);
                float4 q2 = *(const float4*)(As2 + ab);
                pa.x += q1.x + q2.x; pa.y += q1.y + q2.y;
                pa.z += q1.z + q2.z; pa.w += q1.w + q2.w;
            }
            pb0 = *(const float4*)(Bm + (long)(kb + kk0) * Dsz + col0 + nq0 * 4);
            pb1 = *(const float4*)(Bm + (long)(kb + kk0 + 8) * Dsz + col0 + nq0 * 4);
        }

        #pragma unroll
        for (int kk = 0; kk < 16; kk++) {
            ull aa[4];
            #pragma unroll
            for (int u = 0; u < 4; u++) aa[u] = AsU[kk][ty + 16 * u];
            const ull* brow = (const ull*)&Bs[kk][0];
            #pragma unroll
            for (int v = 0; v < 4; v++) {
                ull bb = brow[tx + 16 * v];
                #pragma unroll
                for (int u = 0; u < 4; u++) fma2(acc[u][v], aa[u], bb);
            }
        }
    }

    #pragma unroll
    for (int u = 0; u < 4; u++) {
        long rbase = ((long)(row0 + ty + 16 * u) * Dsz + col0) >> 1;
        #pragma unroll
        for (int v = 0; v < 4; v++) {
            float2 r;
            asm("mov.b64 {%0, %1}, %2;" : "=f"(r.x), "=f"(r.y) : "l"(acc[u][v]));
            ((float2*)Cc)[rbase + tx + 16 * v] = r;
        }
    }
}

// Variant 1: A plain (GEMM1: H = hidden @ w_span[z])
__device__ __forceinline__ void sgemm1_body(
    int e, const float* __restrict__ hidden,
    const float* __restrict__ w_span, char* raw)
{
    const int nb = e % 6, mb = (e / 6) % 8, zi = e / 48;
    const int z = zi / KSPLIT, ks = zi % KSPLIT;
    sgemm_compute(hidden,
                  w_span + (long)z * Dsz * Dsz,
                  g_H + (long)z * HS + (long)ks * 2 * HS,
                  ks * KH, mb * 64, nb * 128, nullptr, nullptr, raw);
}

// Variant 3: A summed from 3 partials (GEMM2: A = (sum H) @ w_p1)
__device__ __forceinline__ void sgemm3_body(
    int e, const float* __restrict__ w_p1, char* raw)
{
    const int nb = e % 6, mb = (e / 6) % 8, zi = e / 48;
    const int z = zi / KSPLIT, ks = zi % KSPLIT;
    const float* A0 = g_H + (long)z * HS;
    sgemm_compute(A0, w_p1,
                  g_A + (long)z * HS + (long)ks * 2 * HS,
                  ks * KH, mb * 64, nb * 128,
                  A0 + 2 * HS, A0 + 4 * HS, raw);
}

// ---------------------------------------------------------------------------
// GEMV-64 body: out[n0+nl] = (sum_k src(k) * W[k*ldw + n]) + bias[n]
// 256 thr = 64 n x 4 k-groups of 192.  mode 0: a1 ; 1: a1+a2 ; 2: relu(a1)
// ---------------------------------------------------------------------------
__device__ __forceinline__ void gemv_body(
    const float* __restrict__ a1, const float* __restrict__ a2, int mode,
    const float* __restrict__ W, int ldw,
    const float* __restrict__ bias, float* __restrict__ out,
    int n0, char* raw)
{
    float (*red)[64] = (float(*)[64])raw;
    const int tid = threadIdx.x;
    const int nl = tid & 63, kg = tid >> 6;
    const int n = n0 + nl;
    float s = 0.f;
    const int k0 = kg * 192;
    #pragma unroll 8
    for (int t = 0; t < 192; t++) {
        int k = k0 + t;
        float av = a1[k];
        if (mode == 1) av += a2[k];
        else if (mode == 2) av = fmaxf(av, 0.f);
        s += av * W[(long)k * ldw + n];
    }
    red[kg][nl] = s;
    __syncthreads();
    if (kg == 0)
        out[n] = red[0][nl] + red[1][nl] + red[2][nl] + red[3][nl] + bias[n];
}

// ---------------------------------------------------------------------------
// L1: [0,288) sgemm H ; [288,324) W3 ; [324,336) C-pad row
// ---------------------------------------------------------------------------
__global__ __launch_bounds__(256, 3) void L1_k(
    const float* __restrict__ hidden, const float* __restrict__ width_emb,
    const float* __restrict__ w_span, const float* __restrict__ b_span,
    const float* __restrict__ w_p1, const float* __restrict__ b_p1)
{
    __shared__ __align__(16) char raw[RAW_BYTES];
    int e = blockIdx.x;
    if (e < 288) {
        sgemm1_body(e, hidden, w_span, raw);
    } else if (e < 324) {
        int g = e - 288, m = g / 12, nb = g % 12;
        gemv_body(width_emb + m * Dsz, nullptr, 0,
                  w_span + 2L * Dsz * Dsz, Dsz,
                  g_zero, g_W3 + m * Dsz, nb * 64, raw);
    } else {
        int nb = e - 324;
        gemv_body(b_span, nullptr, 0, w_p1, Dsz, b_p1, g_C + 3 * Dsz,
                  nb * 64, raw);
    }
}

// ---------------------------------------------------------------------------
// L2: [0,288) sgemm A ; [288,324) C rows 0..2 ; [324,326) projpad ;
//     [326,455) dots
// ---------------------------------------------------------------------------
__global__ __launch_bounds__(256, 3) void L2_k(
    const float* __restrict__ w_p1, const float* __restrict__ b_p1,
    const float* __restrict__ b_span, const float* __restrict__ w_cls,
    const float* __restrict__ b_cls, const float* __restrict__ w_p2,
    const float* __restrict__ b_p2)
{
    __shared__ __align__(16) char raw[RAW_BYTES];
    int e = blockIdx.x;
    if (e < 288) {
        sgemm3_body(e, w_p1, raw);
    } else if (e < 324) {
        int g = e - 288, m = g / 12, nb = g % 12;
        gemv_body(g_W3 + m * Dsz, b_span, 1, w_p1, Dsz, b_p1,
                  g_C + m * Dsz, nb * 64, raw);
    } else if (e < 326) {
        int nb = e - 324;
        gemv_body(g_C + 3 * Dsz, nullptr, 2, w_p2, PD, b_p2, g_projpad,
                  nb * 64, raw);
    } else {
        int gw = (e - 326) * 8 + (threadIdx.x >> 5);
        int lane = threadIdx.x & 31;
        if (gw >= 1028) return;
        float s = 0.f;
        if (gw < 1024) {
            int z = gw >> 9, row = gw & 511;
            const float* base = g_H + (long)z * HS + (long)row * Dsz;
            for (int k = lane; k < Dsz; k += 32)
                s += (base[k] + base[2 * HS + k] + base[4 * HS + k]) * w_cls[k];
        } else {
            const float* v = (gw < 1027) ? (g_W3 + (gw - 1024) * Dsz) : b_span;
            for (int k = lane; k < Dsz; k += 32) s += v[k] * w_cls[k];
        }
        #pragma unroll
        for (int o = 16; o > 0; o >>= 1) s += __shfl_down_sync(0xffffffffu, s, o);
        if (lane == 0) g_L[gw] = s + (gw == 1027 ? b_cls[0] : 0.f);
    }
}

// ---------------------------------------------------------------------------
// L3: [0,96) spanproj ; [96,353) logits ; [353,8386) fillpad
// ---------------------------------------------------------------------------
__global__ __launch_bounds__(256, 2) void L3_k(
    const float* __restrict__ w_p2, const float* __restrict__ b_p2,
    float* __restrict__ out)
{
    int e = blockIdx.x;
    if (e < 96) {
        __shared__ float Xs[16][17];
        __shared__ float Ws[16][PD];
        __shared__ int offA1[16], offA2[16], offC[16];
        __shared__ long offOut[16];

        int tid = threadIdx.x;
        int m0 = e * 16;
        if (tid < 16) {
            int msp = m0 + tid;
            int b = 0, i = 0, w = 0;
            bool valid = msp < 2 * NV;
            int kv = 0;
            if (valid) {
                b = msp / NV; kv = msp - b * NV;
                if (kv < 762)      { i = kv / 3; w = kv - 3 * i; }
                else if (kv < 764) { i = 254;   w = kv - 762;   }
                else               { i = 255;   w = 0;          }
            }
            int j = i + w;
            offA1[tid] = (b * Ssz + i) * Dsz;
            offA2[tid] = (int)HS + (b * Ssz + j) * Dsz;
            offC[tid]  = w * Dsz;
            offOut[tid] = valid ? ((long)Bsz * TOT + ((long)b * TOT + kv) * PD) : -1L;
        }
        __syncthreads();

        int tx = tid & 31, ty = tid >> 5;
        float acc[2][4] = {};
        for (int k0 = 0; k0 < Dsz; k0 += 16) {
            {
                int m = tid >> 4, kk = tid & 15;
                long o1 = offA1[m] + k0 + kk, o2 = offA2[m] + k0 + kk;
                float v = g_A[o1] + g_A[o1 + 2 * HS] + g_A[o1 + 4 * HS]
                        + g_A[o2] + g_A[o2 + 2 * HS] + g_A[o2 + 4 * HS]
                        + g_C[offC[m] + k0 + kk];
                Xs[kk][m] = fmaxf(v, 0.f);
            }
            #pragma unroll
            for (int l = 0; l < 8; l++) {
                int idx = tid + l * 256;
                int kk = idx >> 7, n = idx & 127;
                Ws[kk][n] = w_p2[(long)(k0 + kk) * PD + n];
            }
            __syncthreads();
            #pragma unroll
            for (int kk = 0; kk < 16; kk++) {
                float a0 = Xs[kk][ty], a1 = Xs[kk][ty + 8];
                #pragma unroll
                for (int v = 0; v < 4; v++) {
                    float bb = Ws[kk][tx + 32 * v];
                    acc[0][v] += a0 * bb;
                    acc[1][v] += a1 * bb;
                }
            }
            __syncthreads();
        }
        #pragma unroll
        for (int u = 0; u < 2; u++) {
            int m = ty + 8 * u;
            long ob = offOut[m];
            if (ob >= 0) {
                #pragma unroll
                for (int v = 0; v < 4; v++) {
                    int n = tx + 32 * v;
                    out[ob + n] = acc[u][v] + b_p2[n];
                }
            }
        }
    } else if (e < 353) {
        int idx = (e - 96) * 256 + threadIdx.x;
        if (idx >= Bsz * TOT) return;
        int b = idx / TOT, t = idx - b * TOT;
        float v;
        if (t < NV) {
            int i, w;
            if (t < 762)      { i = t / 3; w = t - 3 * i; }
            else if (t < 764) { i = 254;  w = t - 762;   }
            else              { i = 255;  w = 0;         }
            int j = i + w;
            v = g_L[b * Ssz + i] + g_L[512 + b * Ssz + j] + g_L[1024 + w] + g_L[1027];
        } else {
            v = g_L[1027];
        }
        out[idx] = v;
    } else {
        const int PADROWS = TOT - NV;
        long idx = (long)(e - 353) * 256 + threadIdx.x;
        if (idx >= (long)Bsz * PADROWS * 32) return;
        int r = (int)(idx >> 5), c = (int)(idx & 31);
        int b = r / PADROWS;
        int kk = NV + (r - b * PADROWS);
        float4 val = ((const float4*)g_projpad)[c];
        long f4 = (long)(Bsz * TOT) / 4 + ((long)b * TOT + kk) * (PD / 4) + c;
        ((float4*)out)[f4] = val;
    }
}

// ---------------------------------------------------------------------------
extern "C" void kernel_launch(void* const* d_in, const int* in_sizes, int n_in,
                              void* d_out, int out_size)
{
    const float* hidden    = (const float*)d_in[0];
    const float* width_emb = (const float*)d_in[1];
    const float* w_span    = (const float*)d_in[2];
    const float* b_span    = (const float*)d_in[3];
    const float* w_cls     = (const float*)d_in[4];
    const float* b_cls     = (const float*)d_in[5];
    const float* w_p1      = (const float*)d_in[6];
    const float* b_p1      = (const float*)d_in[7];
    const float* w_p2      = (const float*)d_in[8];
    const float* b_p2      = (const float*)d_in[9];
    float* out = (float*)d_out;

    L1_k<<<336, 256>>>(hidden, width_emb, w_span, b_span, w_p1, b_p1);
    L2_k<<<455, 256>>>(w_p1, b_p1, b_span, w_cls, b_cls, w_p2, b_p2);
    L3_k<<<8386, 256>>>(w_p2, b_p2, out);
}

// round 9
// speedup vs baseline: 1.1797x; 1.1430x over previous
#include <cuda_runtime.h>
#include <cuda_bf16.h>
#include <cstdint>

#define Dsz 768
#define Bsz 2
#define Ssz 256
#define NV  765
#define TOT 32896
#define PD  128
#define HS  393216L        // 512*768 (z stride in elems)
#define WS  589824L        // 768*768

typedef __nv_bfloat16 bf16;
typedef __nv_bfloat162 bf162;

// ---------------- scratch (device globals; no allocation) ------------------
__device__ __align__(16) bf16 g_hh[Bsz*Ssz*Dsz], g_hl[Bsz*Ssz*Dsz];     // hidden hi/lo
__device__ __align__(16) bf16 g_wsTh[2*WS],      g_wsTl[2*WS];          // w_span[z]^T [n][k] hi/lo
__device__ __align__(16) bf16 g_wp1Th[WS],       g_wp1Tl[WS];           // w_p1^T [n][k] hi/lo
__device__ __align__(16) bf16 g_Hh[2*Bsz*Ssz*Dsz], g_Hl[2*Bsz*Ssz*Dsz]; // H hi/lo [z][512][768]
__device__ __align__(16) float g_A[2*Bsz*Ssz*Dsz];                      // A [z][512][768]
__device__ float g_W3[3*Dsz];
__device__ float g_C[4*Dsz];          // 0..2: (W3[w]+b_span)@w_p1+b_p1 ; 3: cpad
__device__ float g_L[1028];
__device__ __align__(16) float g_projpad[PD];
__device__ float g_zero[Dsz];

// ---------------------------------------------------------------------------
__device__ __forceinline__ void mma_bf16(float* c, const unsigned* a,
                                         const unsigned* b) {
    asm volatile(
        "mma.sync.aligned.m16n8k16.row.col.f32.bf16.bf16.f32 "
        "{%0,%1,%2,%3}, {%4,%5,%6,%7}, {%8,%9}, {%0,%1,%2,%3};"
        : "+f"(c[0]), "+f"(c[1]), "+f"(c[2]), "+f"(c[3])
        : "r"(a[0]), "r"(a[1]), "r"(a[2]), "r"(a[3]), "r"(b[0]), "r"(b[1]));
}

#define KST 24   // smem row stride in bf16 (48B: conflict-free frag reads, 16B-aligned)

// ---------------------------------------------------------------------------
// MMA GEMM tile: D[64 x 64] = A[64 x 768] * B[64 x 768]^T (B given as [n][k]).
// bf16 hi/lo split: Ah*Bh + Ah*Bl + Al*Bh, fp32 accum.
// 128 threads = 4 warps of 32x32 (2x4 m16n8k16 tiles).  K in 48 chunks of 16.
// e in [0,192): z = e/96 ; r = e%96: row0 = (r/12)*64, n0 = (r%12)*64.
// outMode 1: bf16 hi/lo to g_Hh/g_Hl ; 2: fp32 to g_A.
// ---------------------------------------------------------------------------
__device__ void tmma_body(int e,
    const bf16* __restrict__ Ah0, const bf16* __restrict__ Al0, long aZ,
    const bf16* __restrict__ Bh0, const bf16* __restrict__ Bl0, long bZ,
    int outMode)
{
    __shared__ __align__(16) bf16 sA[2][2][64][KST];   // [buf][hi/lo][row][k]
    __shared__ __align__(16) bf16 sB[2][2][64][KST];

    const int z = e / 96, r = e % 96;
    const int row0 = (r / 12) * 64, n0 = (r % 12) * 64;
    const bf16* Ah = Ah0 + (long)z * aZ;
    const bf16* Al = Al0 + (long)z * aZ;
    const bf16* Bh = Bh0 + (long)z * bZ;
    const bf16* Bl = Bl0 + (long)z * bZ;

    const int tid = threadIdx.x, wid = tid >> 5, lane = tid & 31;
    const int wr = wid >> 1, wc = wid & 1;
    const int gid = lane >> 2, kp = lane & 3;

    // gmem loader: thread covers one 16B chunk per matrix per iter
    const int lr = tid >> 1, lh = (tid & 1) * 8;
    const long aoff = (long)(row0 + lr) * Dsz + lh;
    const long boff = (long)(n0 + lr) * Dsz + lh;

    float acc[2][4][4] = {};
    uint4 pAh, pAl, pBh, pBl;

    pAh = *(const uint4*)(Ah + aoff);
    pAl = *(const uint4*)(Al + aoff);
    pBh = *(const uint4*)(Bh + boff);
    pBl = *(const uint4*)(Bl + boff);
    *(uint4*)&sA[0][0][lr][lh] = pAh;
    *(uint4*)&sA[0][1][lr][lh] = pAl;
    *(uint4*)&sB[0][0][lr][lh] = pBh;
    *(uint4*)&sB[0][1][lr][lh] = pBl;
    __syncthreads();

    for (int it = 0; it < 48; it++) {
        const int cur = it & 1;
        if (it + 1 < 48) {
            const int kb = (it + 1) * 16;
            pAh = *(const uint4*)(Ah + aoff + kb);
            pAl = *(const uint4*)(Al + aoff + kb);
            pBh = *(const uint4*)(Bh + boff + kb);
            pBl = *(const uint4*)(Bl + boff + kb);
        }

        unsigned ah[2][4], al[2][4], bh[4][2], bl[4][2];
        #pragma unroll
        for (int mt = 0; mt < 2; mt++) {
            const int r0 = wr * 32 + mt * 16 + gid;
            ah[mt][0] = *(const unsigned*)&sA[cur][0][r0][kp * 2];
            ah[mt][1] = *(const unsigned*)&sA[cur][0][r0 + 8][kp * 2];
            ah[mt][2] = *(const unsigned*)&sA[cur][0][r0][kp * 2 + 8];
            ah[mt][3] = *(const unsigned*)&sA[cur][0][r0 + 8][kp * 2 + 8];
            al[mt][0] = *(const unsigned*)&sA[cur][1][r0][kp * 2];
            al[mt][1] = *(const unsigned*)&sA[cur][1][r0 + 8][kp * 2];
            al[mt][2] = *(const unsigned*)&sA[cur][1][r0][kp * 2 + 8];
            al[mt][3] = *(const unsigned*)&sA[cur][1][r0 + 8][kp * 2 + 8];
        }
        #pragma unroll
        for (int nt = 0; nt < 4; nt++) {
            const int rb = wc * 32 + nt * 8 + gid;
            bh[nt][0] = *(const unsigned*)&sB[cur][0][rb][kp * 2];
            bh[nt][1] = *(const unsigned*)&sB[cur][0][rb][kp * 2 + 8];
            bl[nt][0] = *(const unsigned*)&sB[cur][1][rb][kp * 2];
            bl[nt][1] = *(const unsigned*)&sB[cur][1][rb][kp * 2 + 8];
        }
        #pragma unroll
        for (int mt = 0; mt < 2; mt++)
            #pragma unroll
            for (int nt = 0; nt < 4; nt++) {
                mma_bf16(acc[mt][nt], ah[mt], bh[nt]);
                mma_bf16(acc[mt][nt], ah[mt], bl[nt]);
                mma_bf16(acc[mt][nt], al[mt], bh[nt]);
            }

        if (it + 1 < 48) {
            const int nb = cur ^ 1;
            *(uint4*)&sA[nb][0][lr][lh] = pAh;
            *(uint4*)&sA[nb][1][lr][lh] = pAl;
            *(uint4*)&sB[nb][0][lr][lh] = pBh;
            *(uint4*)&sB[nb][1][lr][lh] = pBl;
            __syncthreads();
        }
    }

    // epilogue: c0,c1 -> (row=gid, col=kp*2+{0,1}); c2,c3 -> row gid+8
    #pragma unroll
    for (int mt = 0; mt < 2; mt++) {
        const int grow = row0 + wr * 32 + mt * 16 + gid;
        const long gr0 = ((long)z * 512 + grow) * Dsz;
        const long gr1 = gr0 + 8L * Dsz;
        #pragma unroll
        for (int nt = 0; nt < 4; nt++) {
            const int gc = n0 + wc * 32 + nt * 8 + kp * 2;
            const float* cc = acc[mt][nt];
            if (outMode == 1) {
                bf162 h01 = __floats2bfloat162_rn(cc[0], cc[1]);
                bf162 l01 = __floats2bfloat162_rn(cc[0] - __low2float(h01),
                                                  cc[1] - __high2float(h01));
                bf162 h23 = __floats2bfloat162_rn(cc[2], cc[3]);
                bf162 l23 = __floats2bfloat162_rn(cc[2] - __low2float(h23),
                                                  cc[3] - __high2float(h23));
                *(bf162*)&g_Hh[gr0 + gc] = h01;
                *(bf162*)&g_Hl[gr0 + gc] = l01;
                *(bf162*)&g_Hh[gr1 + gc] = h23;
                *(bf162*)&g_Hl[gr1 + gc] = l23;
            } else {
                float2 v0 = { cc[0], cc[1] }, v1 = { cc[2], cc[3] };
                *(float2*)&g_A[gr0 + gc] = v0;
                *(float2*)&g_A[gr1 + gc] = v1;
            }
        }
    }
}

// ---------------------------------------------------------------------------
// GEMV-64 (256 thr): 64 n x 4 k-groups of 192.  mode 0: a1 ; 1: a1+a2 ; 2: relu
// ---------------------------------------------------------------------------
__device__ __forceinline__ void gemv256(
    const float* __restrict__ a1, const float* __restrict__ a2, int mode,
    const float* __restrict__ W, int ldw,
    const float* __restrict__ bias, float* __restrict__ out,
    int n0, char* raw)
{
    float (*red)[64] = (float(*)[64])raw;
    const int tid = threadIdx.x;
    const int nl = tid & 63, kg = tid >> 6;
    const int n = n0 + nl;
    float s = 0.f;
    const int k0 = kg * 192;
    #pragma unroll 8
    for (int t = 0; t < 192; t++) {
        int k = k0 + t;
        float av = a1[k];
        if (mode == 1) av += a2[k];
        else if (mode == 2) av = fmaxf(av, 0.f);
        s += av * W[(long)k * ldw + n];
    }
    red[kg][nl] = s;
    __syncthreads();
    if (kg == 0)
        out[n] = red[0][nl] + red[1][nl] + red[2][nl] + red[3][nl] + bias[n];
}

// GEMV-64 (128 thr): 64 n x 2 k-groups of 384
__device__ __forceinline__ void gemv128(
    const float* __restrict__ a1, const float* __restrict__ a2, int mode,
    const float* __restrict__ W, int ldw,
    const float* __restrict__ bias, float* __restrict__ out, int n0)
{
    __shared__ float red[2][64];
    const int tid = threadIdx.x;
    const int nl = tid & 63, kg = tid >> 6;
    const int n = n0 + nl;
    float s = 0.f;
    const int k0 = kg * 384;
    #pragma unroll 8
    for (int t = 0; t < 384; t++) {
        int k = k0 + t;
        float av = a1[k];
        if (mode == 1) av += a2[k];
        else if (mode == 2) av = fmaxf(av, 0.f);
        s += av * W[(long)k * ldw + n];
    }
    red[kg][nl] = s;
    __syncthreads();
    if (kg == 0) out[n] = red[0][nl] + red[1][nl] + bias[n];
}

// ---------------------------------------------------------------------------
// P0 (256 thr): [0,432) weight transpose+convert ; [432,624) hidden convert ;
//               [624,660) W3 gemv ; [660,672) cpad gemv
// ---------------------------------------------------------------------------
__global__ void P0_k(const float* __restrict__ hidden,
                     const float* __restrict__ w_span,
                     const float* __restrict__ w_p1,
                     const float* __restrict__ width_emb,
                     const float* __restrict__ b_span,
                     const float* __restrict__ b_p1)
{
    __shared__ __align__(16) char raw[64 * 65 * 4];
    int e = blockIdx.x, tid = threadIdx.x;
    if (e < 432) {
        int m = e / 144, t = e % 144;
        int tr = t / 12, tc = t % 12;           // tr: n tile, tc: k tile
        const float* src = (m < 2) ? (w_span + (long)m * WS) : w_p1;
        bf16* dh = (m < 2) ? (g_wsTh + (long)m * WS) : g_wp1Th;
        bf16* dl = (m < 2) ? (g_wsTl + (long)m * WS) : g_wp1Tl;
        int n0 = tr * 64, k0 = tc * 64;
        float (*ts)[65] = (float(*)[65])raw;
        {
            int r = tid >> 2, cs = (tid & 3) * 16;
            const float* sp = src + (long)(k0 + r) * Dsz + n0 + cs;
            #pragma unroll
            for (int i = 0; i < 16; i++) ts[r][cs + i] = sp[i];
        }
        __syncthreads();
        {
            int rr = tid >> 2, ks = (tid & 3) * 16;
            long go = (long)(n0 + rr) * Dsz + k0 + ks;
            #pragma unroll
            for (int i = 0; i < 16; i++) {
                float x = ts[ks + i][rr];
                bf16 h = __float2bfloat16(x);
                dh[go + i] = h;
                dl[go + i] = __float2bfloat16(x - __bfloat162float(h));
            }
        }
    } else if (e < 624) {
        long base = (long)(e - 432) * 2048 + tid * 8;
        float4 a = *(const float4*)(hidden + base);
        float4 b = *(const float4*)(hidden + base + 4);
        float xs[8] = { a.x, a.y, a.z, a.w, b.x, b.y, b.z, b.w };
        __align__(16) bf16 h8[8], l8[8];
        #pragma unroll
        for (int i = 0; i < 8; i++) {
            bf16 h = __float2bfloat16(xs[i]);
            h8[i] = h;
            l8[i] = __float2bfloat16(xs[i] - __bfloat162float(h));
        }
        *(uint4*)(g_hh + base) = *(const uint4*)h8;
        *(uint4*)(g_hl + base) = *(const uint4*)l8;
    } else if (e < 660) {
        int g = e - 624, m = g / 12, nb = g % 12;
        gemv256(width_emb + m * Dsz, nullptr, 0,
                w_span + 2L * Dsz * Dsz, Dsz,
                g_zero, g_W3 + m * Dsz, nb * 64, raw);
    } else {
        int nb = e - 660;
        gemv256(b_span, nullptr, 0, w_p1, Dsz, b_p1, g_C + 3 * Dsz,
                nb * 64, raw);
    }
}

// ---------------------------------------------------------------------------
// P1 (128 thr): [0,192) MMA GEMM1 (H) ; [192,228) C rows ; [228,230) projpad
// ---------------------------------------------------------------------------
__global__ __launch_bounds__(128, 4) void P1_k(
    const float* __restrict__ b_span, const float* __restrict__ w_p1,
    const float* __restrict__ b_p1, const float* __restrict__ w_p2,
    const float* __restrict__ b_p2)
{
    int e = blockIdx.x;
    if (e < 192) {
        tmma_body(e, g_hh, g_hl, 0L, g_wsTh, g_wsTl, WS, 1);
    } else if (e < 228) {
        int g = e - 192, m = g / 12, nb = g % 12;
        gemv128(g_W3 + m * Dsz, b_span, 1, w_p1, Dsz, b_p1,
                g_C + m * Dsz, nb * 64);
    } else {
        int nb = e - 228;
        gemv128(g_C + 3 * Dsz, nullptr, 2, w_p2, PD, b_p2, g_projpad,
                nb * 64);
    }
}

// ---------------------------------------------------------------------------
// P2 (128 thr): [0,192) MMA GEMM2 (A) ; [192,449) classifier dots
// ---------------------------------------------------------------------------
__global__ __launch_bounds__(128, 4) void P2_k(
    const float* __restrict__ w_cls, const float* __restrict__ b_cls,
    const float* __restrict__ b_span)
{
    int e = blockIdx.x;
    if (e < 192) {
        tmma_body(e, g_Hh, g_Hl, HS, g_wp1Th, g_wp1Tl, 0L, 2);
    } else {
        int gw = (e - 192) * 4 + (threadIdx.x >> 5);
        int lane = threadIdx.x & 31;
        if (gw >= 1028) return;
        float s = 0.f;
        if (gw < 1024) {
            int z = gw >> 9, row = gw & 511;
            const bf16* bh = g_Hh + (long)z * HS + (long)row * Dsz;
            const bf16* bl = g_Hl + (long)z * HS + (long)row * Dsz;
            for (int k = lane; k < Dsz; k += 32)
                s += (__bfloat162float(bh[k]) + __bfloat162float(bl[k])) * w_cls[k];
        } else {
            const float* v = (gw < 1027) ? (g_W3 + (gw - 1024) * Dsz) : b_span;
            for (int k = lane; k < Dsz; k += 32) s += v[k] * w_cls[k];
        }
        #pragma unroll
        for (int o = 16; o > 0; o >>= 1) s += __shfl_down_sync(0xffffffffu, s, o);
        if (lane == 0) g_L[gw] = s + (gw == 1027 ? b_cls[0] : 0.f);
    }
}

// ---------------------------------------------------------------------------
// P3 (256 thr): [0,96) spanproj ; [96,353) logits ; [353,8386) fillpad
// ---------------------------------------------------------------------------
__global__ __launch_bounds__(256, 2) void P3_k(
    const float* __restrict__ w_p2, const float* __restrict__ b_p2,
    float* __restrict__ out)
{
    int e = blockIdx.x;
    if (e < 96) {
        __shared__ float Xs[16][17];
        __shared__ float Ws[16][PD];
        __shared__ int offA1[16], offA2[16], offC[16];
        __shared__ long offOut[16];

        int tid = threadIdx.x;
        int m0 = e * 16;
        if (tid < 16) {
            int msp = m0 + tid;
            int b = 0, i = 0, w = 0;
            bool valid = msp < 2 * NV;
            int kv = 0;
            if (valid) {
                b = msp / NV; kv = msp - b * NV;
                if (kv < 762)      { i = kv / 3; w = kv - 3 * i; }
                else if (kv < 764) { i = 254;   w = kv - 762;   }
                else               { i = 255;   w = 0;          }
            }
            int j = i + w;
            offA1[tid] = (b * Ssz + i) * Dsz;
            offA2[tid] = (int)HS + (b * Ssz + j) * Dsz;
            offC[tid]  = w * Dsz;
            offOut[tid] = valid ? ((long)Bsz * TOT + ((long)b * TOT + kv) * PD) : -1L;
        }
        __syncthreads();

        int tx = tid & 31, ty = tid >> 5;
        float acc[2][4] = {};
        for (int k0 = 0; k0 < Dsz; k0 += 16) {
            {
                int m = tid >> 4, kk = tid & 15;
                float v = g_A[offA1[m] + k0 + kk] + g_A[offA2[m] + k0 + kk]
                        + g_C[offC[m] + k0 + kk];
                Xs[kk][m] = fmaxf(v, 0.f);
            }
            #pragma unroll
            for (int l = 0; l < 8; l++) {
                int idx = tid + l * 256;
                int kk = idx >> 7, n = idx & 127;
                Ws[kk][n] = w_p2[(long)(k0 + kk) * PD + n];
            }
            __syncthreads();
            #pragma unroll
            for (int kk = 0; kk < 16; kk++) {
                float a0 = Xs[kk][ty], a1 = Xs[kk][ty + 8];
                #pragma unroll
                for (int v = 0; v < 4; v++) {
                    float bb = Ws[kk][tx + 32 * v];
                    acc[0][v] += a0 * bb;
                    acc[1][v] += a1 * bb;
                }
            }
            __syncthreads();
        }
        #pragma unroll
        for (int u = 0; u < 2; u++) {
            int m = ty + 8 * u;
            long ob = offOut[m];
            if (ob >= 0) {
                #pragma unroll
                for (int v = 0; v < 4; v++) {
                    int n = tx + 32 * v;
                    out[ob + n] = acc[u][v] + b_p2[n];
                }
            }
        }
    } else if (e < 353) {
        int idx = (e - 96) * 256 + threadIdx.x;
        if (idx >= Bsz * TOT) return;
        int b = idx / TOT, t = idx - b * TOT;
        float v;
        if (t < NV) {
            int i, w;
            if (t < 762)      { i = t / 3; w = t - 3 * i; }
            else if (t < 764) { i = 254;  w = t - 762;   }
            else              { i = 255;  w = 0;         }
            int j = i + w;
            v = g_L[b * Ssz + i] + g_L[512 + b * Ssz + j] + g_L[1024 + w] + g_L[1027];
        } else {
            v = g_L[1027];
        }
        out[idx] = v;
    } else {
        const int PADROWS = TOT - NV;
        long idx = (long)(e - 353) * 256 + threadIdx.x;
        if (idx >= (long)Bsz * PADROWS * 32) return;
        int r = (int)(idx >> 5), c = (int)(idx & 31);
        int b = r / PADROWS;
        int kk = NV + (r - b * PADROWS);
        float4 val = ((const float4*)g_projpad)[c];
        long f4 = (long)(Bsz * TOT) / 4 + ((long)b * TOT + kk) * (PD / 4) + c;
        ((float4*)out)[f4] = val;
    }
}

// ---------------------------------------------------------------------------
extern "C" void kernel_launch(void* const* d_in, const int* in_sizes, int n_in,
                              void* d_out, int out_size)
{
    const float* hidden    = (const float*)d_in[0];
    const float* width_emb = (const float*)d_in[1];
    const float* w_span    = (const float*)d_in[2];
    const float* b_span    = (const float*)d_in[3];
    const float* w_cls     = (const float*)d_in[4];
    const float* b_cls     = (const float*)d_in[5];
    const float* w_p1      = (const float*)d_in[6];
    const float* b_p1      = (const float*)d_in[7];
    const float* w_p2      = (const float*)d_in[8];
    const float* b_p2      = (const float*)d_in[9];
    float* out = (float*)d_out;

    P0_k<<<672, 256>>>(hidden, w_span, w_p1, width_emb, b_span, b_p1);
    P1_k<<<230, 128>>>(b_span, w_p1, b_p1, w_p2, b_p2);
    P2_k<<<449, 128>>>(w_cls, b_cls, b_span);
    P3_k<<<8386, 256>>>(w_p2, b_p2, out);
}